// round 1
// baseline (speedup 1.0000x reference)
#include <cuda_runtime.h>

// Problem constants
#define BB   16
#define LSEQ 1024
#define DIN  512
#define NKC  512      // num kernels (channels)
#define HH   8        // heads
#define DHH  64       // dh = NKC/HH
#define LC   1022     // Lc = L - 2 (VALID conv, width 3)
#define LCP  1024     // padded Lc
#define NLB  1024     // num labels
#define ADIM 256      // attention dim
#define KCONV 1536    // 3*DIN
#define SA   66       // smem row stride (conflict-free both load orders, 8B aligned)

// ---------------- scratch (__device__ globals; zero-initialized at load; pads never written) ----------
__device__ float g_q1[BB * NKC * LCP];          // [B][NK][LCP]
__device__ float g_k1[BB * NKC * LCP];
__device__ float g_v1[BB * NKC * LCP];
__device__ float g_attn[128 * 1024 * 1024];     // [B*H][LCP][LCP]  (537 MB)
__device__ float g_c1[BB * LC * NKC];           // cnn_out1 [B][LC][NK]
__device__ float g_t1[BB * LC * ADIM];          // tanh(C1 @ W1^T)  [B][LC][AD]
__device__ float g_sc[BB * NLB * LCP];          // label-sum scores [B][NL][LCP]
__device__ float g_b2s[BB * NLB * LCP];         // cross-attn scores [B][NL][LCP]
__device__ float g_o1[BB * NLB * NKC];          // out1 pre-norm
__device__ float g_o2[BB * NLB * NKC];          // out2 pre-norm

// ---------------- packed f32x2 helpers ----------------
__device__ __forceinline__ unsigned long long pk2(float lo, float hi) {
    unsigned long long r;
    asm("mov.b64 %0, {%1, %2};" : "=l"(r) : "f"(lo), "f"(hi));
    return r;
}
__device__ __forceinline__ void fma2(unsigned long long& d, unsigned long long a, unsigned long long b) {
    asm("fma.rn.f32x2 %0, %1, %2, %0;" : "+l"(d) : "l"(a), "l"(b));
}
__device__ __forceinline__ float2 up2(unsigned long long v) {
    float lo, hi;
    asm("mov.b64 {%0, %1}, %2;" : "=f"(lo), "=f"(hi) : "l"(v));
    return make_float2(lo, hi);
}

// 64x64x16 tile microkernel: C[ty*4+i][tx*4 + j] accumulated in f32x2 pairs
__device__ __forceinline__ void mm16(const float* __restrict__ As, const float* __restrict__ Bs,
                                     int ty, int tx, unsigned long long (&acc)[4][2]) {
#pragma unroll
    for (int kk = 0; kk < 16; ++kk) {
        const float* ap = As + kk * SA + ty * 4;
        const float* bp = Bs + kk * SA + tx * 4;
        float2 a01 = *(const float2*)ap;
        float2 a23 = *(const float2*)(ap + 2);
        float2 b01 = *(const float2*)bp;
        float2 b23 = *(const float2*)(bp + 2);
        unsigned long long bb0 = pk2(b01.x, b01.y);
        unsigned long long bb1 = pk2(b23.x, b23.y);
        unsigned long long aa;
        aa = pk2(a01.x, a01.x); fma2(acc[0][0], aa, bb0); fma2(acc[0][1], aa, bb1);
        aa = pk2(a01.y, a01.y); fma2(acc[1][0], aa, bb0); fma2(acc[1][1], aa, bb1);
        aa = pk2(a23.x, a23.x); fma2(acc[2][0], aa, bb0); fma2(acc[2][1], aa, bb1);
        aa = pk2(a23.y, a23.y); fma2(acc[3][0], aa, bb0); fma2(acc[3][1], aa, bb1);
    }
}

// ---------------- 1) conv1d (width 3, VALID) + bias + elu ----------------
// C[o][l] = sum_{t,i} emb[b][l+t][i] * w[o][i][t];  M=o, N=l, K=1536
__global__ void conv_kernel(const float* __restrict__ emb, const float* __restrict__ w,
                            const float* __restrict__ bias, int which) {
    float* out = (which == 0) ? g_q1 : (which == 1) ? g_k1 : g_v1;
    int b = blockIdx.z, o0 = blockIdx.y * 64, l0 = blockIdx.x * 64;
    __shared__ float As[16 * SA], Bs[16 * SA];
    int tid = threadIdx.x, tx = tid & 15, ty = tid >> 4;
    unsigned long long acc[4][2] = {};
    for (int ko = 0; ko < KCONV; ko += 16) {
        int t = ko >> 9, i0 = ko & 511;
        for (int idx = tid; idx < 1024; idx += 256) {
            int kk = idx & 15, mn = idx >> 4;
            As[kk * SA + mn] = w[(o0 + mn) * KCONV + (i0 + kk) * 3 + t];
            int row = l0 + mn + t;
            Bs[kk * SA + mn] = (row < LSEQ) ? emb[((size_t)b * LSEQ + row) * DIN + i0 + kk] : 0.f;
        }
        __syncthreads();
        mm16(As, Bs, ty, tx, acc);
        __syncthreads();
    }
#pragma unroll
    for (int i = 0; i < 4; ++i) {
        int o = o0 + ty * 4 + i;
        float bv = bias[o];
#pragma unroll
        for (int j = 0; j < 2; ++j) {
            float2 v = up2(acc[i][j]);
            int l = l0 + tx * 4 + j * 2;
            float x0 = v.x + bv, x1 = v.y + bv;
            x0 = x0 > 0.f ? x0 : (__expf(x0) - 1.f);
            x1 = x1 > 0.f ? x1 : (__expf(x1) - 1.f);
            if (l < LC)     out[((size_t)b * NKC + o) * LCP + l]     = x0;
            if (l + 1 < LC) out[((size_t)b * NKC + o) * LCP + l + 1] = x1;
        }
    }
}

// ---------------- 2) self-attention scores A[l][m] = (Q^T K)/8 ----------------
__global__ void score_qk_kernel() {
    int z = blockIdx.z, b = z >> 3, h = z & 7;
    int l0 = blockIdx.x * 64, m0 = blockIdx.y * 64;
    const float* qb = g_q1 + ((size_t)b * NKC + h * DHH) * LCP;
    const float* kb = g_k1 + ((size_t)b * NKC + h * DHH) * LCP;
    __shared__ float As[16 * SA], Bs[16 * SA];
    int tid = threadIdx.x, tx = tid & 15, ty = tid >> 4;
    unsigned long long acc[4][2] = {};
    for (int k0 = 0; k0 < DHH; k0 += 16) {
        for (int idx = tid; idx < 1024; idx += 256) {
            int mn = idx & 63, kk = idx >> 6;   // M-fastest (l contiguous in gmem)
            As[kk * SA + mn] = qb[(k0 + kk) * LCP + l0 + mn];
            Bs[kk * SA + mn] = kb[(k0 + kk) * LCP + m0 + mn];
        }
        __syncthreads();
        mm16(As, Bs, ty, tx, acc);
        __syncthreads();
    }
    float* cbase = g_attn + (size_t)z * LCP * LCP;
#pragma unroll
    for (int i = 0; i < 4; ++i) {
        int l = l0 + ty * 4 + i;
        if (l >= LC) continue;
#pragma unroll
        for (int j = 0; j < 2; ++j) {
            float2 v = up2(acc[i][j]);
            int c = m0 + tx * 4 + j * 2;
            if (c < LC)     cbase[(size_t)l * LCP + c]     = v.x * 0.125f;
            if (c + 1 < LC) cbase[(size_t)l * LCP + c + 1] = v.y * 0.125f;
        }
    }
}

// ---------------- softmax over rows of length 1022 (stride 1024) ----------------
__global__ void softmax_kernel(int sel) {
    float* base = (sel == 0) ? g_attn : (sel == 1) ? g_sc : g_b2s;
    float* row = base + ((size_t)blockIdx.y * 1024 + blockIdx.x) * 1024;
    int tid = threadIdx.x;
    float v[4];
    float mx = -1e30f;
#pragma unroll
    for (int j = 0; j < 4; ++j) {
        int idx = tid + j * 256;
        v[j] = (idx < LC) ? row[idx] : -1e30f;
        mx = fmaxf(mx, v[j]);
    }
    __shared__ float red[256];
    red[tid] = mx; __syncthreads();
    for (int s = 128; s > 0; s >>= 1) { if (tid < s) red[tid] = fmaxf(red[tid], red[tid + s]); __syncthreads(); }
    mx = red[0]; __syncthreads();
    float sum = 0.f;
#pragma unroll
    for (int j = 0; j < 4; ++j) {
        int idx = tid + j * 256;
        v[j] = (idx < LC) ? __expf(v[j] - mx) : 0.f;
        sum += v[j];
    }
    red[tid] = sum; __syncthreads();
    for (int s = 128; s > 0; s >>= 1) { if (tid < s) red[tid] += red[tid + s]; __syncthreads(); }
    float inv = 1.f / red[0];
#pragma unroll
    for (int j = 0; j < 4; ++j) {
        int idx = tid + j * 256;
        if (idx < LC) row[idx] = v[j] * inv;
    }
}

// ---------------- 3) attention output -> cnn_out1[b][l][h*64+d] ----------------
// C[l][d] = sum_m P[l][m] * V[d][m];  M=l, N=d(64), K=1022(pad 1024, pads are zero)
__global__ void attn_out_kernel() {
    int z = blockIdx.z, b = z >> 3, h = z & 7;
    int l0 = blockIdx.x * 64;
    const float* prow = g_attn + (size_t)z * LCP * LCP;
    const float* vb = g_v1 + ((size_t)b * NKC + h * DHH) * LCP;
    __shared__ float As[16 * SA], Bs[16 * SA];
    int tid = threadIdx.x, tx = tid & 15, ty = tid >> 4;
    unsigned long long acc[4][2] = {};
    for (int m0 = 0; m0 < LCP; m0 += 16) {
        for (int idx = tid; idx < 1024; idx += 256) {
            int kk = idx & 15, mn = idx >> 4;   // K-fastest (m contiguous)
            As[kk * SA + mn] = prow[(size_t)(l0 + mn) * LCP + m0 + kk];
            Bs[kk * SA + mn] = vb[(size_t)mn * LCP + m0 + kk];
        }
        __syncthreads();
        mm16(As, Bs, ty, tx, acc);
        __syncthreads();
    }
#pragma unroll
    for (int i = 0; i < 4; ++i) {
        int l = l0 + ty * 4 + i;
        if (l >= LC) continue;
#pragma unroll
        for (int j = 0; j < 2; ++j) {
            float2 v = up2(acc[i][j]);
            int d = tx * 4 + j * 2;
            float* dst = g_c1 + ((size_t)(b * LC + l) * NKC + h * DHH + d);
            dst[0] = v.x; dst[1] = v.y;
        }
    }
}

// ---------------- 4) t1 = tanh(C1 @ W1^T):  M=l, N=a(256), K=512 ----------------
__global__ void lsa1_kernel(const float* __restrict__ w1) {
    int b = blockIdx.z, l0 = blockIdx.x * 64, a0 = blockIdx.y * 64;
    __shared__ float As[16 * SA], Bs[16 * SA];
    int tid = threadIdx.x, tx = tid & 15, ty = tid >> 4;
    unsigned long long acc[4][2] = {};
    for (int k0 = 0; k0 < NKC; k0 += 16) {
        for (int idx = tid; idx < 1024; idx += 256) {
            int kk = idx & 15, mn = idx >> 4;
            int row = l0 + mn;
            As[kk * SA + mn] = (row < LC) ? g_c1[(size_t)(b * LC + row) * NKC + k0 + kk] : 0.f;
            Bs[kk * SA + mn] = w1[(a0 + mn) * NKC + k0 + kk];
        }
        __syncthreads();
        mm16(As, Bs, ty, tx, acc);
        __syncthreads();
    }
#pragma unroll
    for (int i = 0; i < 4; ++i) {
        int l = l0 + ty * 4 + i;
        if (l >= LC) continue;
#pragma unroll
        for (int j = 0; j < 2; ++j) {
            float2 v = up2(acc[i][j]);
            int a = a0 + tx * 4 + j * 2;
            float* dst = g_t1 + ((size_t)(b * LC + l) * ADIM + a);
            dst[0] = tanhf(v.x); dst[1] = tanhf(v.y);
        }
    }
}

// ---------------- 5) score[n][l] = sum_a W2[n][a] * t1[l][a]:  M=n, N=l, K=256 ----------------
__global__ void score2_kernel(const float* __restrict__ w2) {
    int b = blockIdx.z, n0 = blockIdx.x * 64, l0 = blockIdx.y * 64;
    __shared__ float As[16 * SA], Bs[16 * SA];
    int tid = threadIdx.x, tx = tid & 15, ty = tid >> 4;
    unsigned long long acc[4][2] = {};
    for (int k0 = 0; k0 < ADIM; k0 += 16) {
        for (int idx = tid; idx < 1024; idx += 256) {
            int kk = idx & 15, mn = idx >> 4;
            As[kk * SA + mn] = w2[(n0 + mn) * ADIM + k0 + kk];
            int row = l0 + mn;
            Bs[kk * SA + mn] = (row < LC) ? g_t1[(size_t)(b * LC + row) * ADIM + k0 + kk] : 0.f;
        }
        __syncthreads();
        mm16(As, Bs, ty, tx, acc);
        __syncthreads();
    }
#pragma unroll
    for (int i = 0; i < 4; ++i) {
        int n = n0 + ty * 4 + i;
#pragma unroll
        for (int j = 0; j < 2; ++j) {
            float2 v = up2(acc[i][j]);
            int l = l0 + tx * 4 + j * 2;
            if (l < LC)     g_sc[(size_t)(b * NLB + n) * LCP + l]     = v.x;
            if (l + 1 < LC) g_sc[(size_t)(b * NLB + n) * LCP + l + 1] = v.y;
        }
    }
}

// ---------------- 6) out1[n][k] = sum_l P[n][l] * C1[l][k]:  M=n, N=k, K=1022 ----------------
__global__ void out1_kernel() {
    int b = blockIdx.z, n0 = blockIdx.x * 64, kc0 = blockIdx.y * 64;
    __shared__ float As[16 * SA], Bs[16 * SA];
    int tid = threadIdx.x, tx = tid & 15, ty = tid >> 4;
    unsigned long long acc[4][2] = {};
    for (int ko = 0; ko < LCP; ko += 16) {
        for (int idx = tid; idx < 1024; idx += 256) {
            int kk = idx & 15, mn = idx >> 4;
            As[kk * SA + mn] = g_sc[(size_t)(b * NLB + n0 + mn) * LCP + ko + kk];  // pads zero
        }
        for (int idx = tid; idx < 1024; idx += 256) {
            int nn = idx & 63, kk = idx >> 6;   // M-fastest (k contiguous)
            int row = ko + kk;
            Bs[kk * SA + nn] = (row < LC) ? g_c1[(size_t)(b * LC + row) * NKC + kc0 + nn] : 0.f;
        }
        __syncthreads();
        mm16(As, Bs, ty, tx, acc);
        __syncthreads();
    }
#pragma unroll
    for (int i = 0; i < 4; ++i) {
        int n = n0 + ty * 4 + i;
#pragma unroll
        for (int j = 0; j < 2; ++j) {
            float2 v = up2(acc[i][j]);
            int k = kc0 + tx * 4 + j * 2;
            float* dst = g_o1 + ((size_t)(b * NLB + n) * NKC + k);
            dst[0] = v.x; dst[1] = v.y;
        }
    }
}

// ---------------- 7) b2[n][l] = sum_k LE[n][k] * K1[k][l]:  M=n, N=l, K=512 ----------------
__global__ void b2_kernel(const float* __restrict__ lab) {
    int b = blockIdx.z, n0 = blockIdx.x * 64, l0 = blockIdx.y * 64;
    __shared__ float As[16 * SA], Bs[16 * SA];
    int tid = threadIdx.x, tx = tid & 15, ty = tid >> 4;
    unsigned long long acc[4][2] = {};
    for (int k0 = 0; k0 < NKC; k0 += 16) {
        for (int idx = tid; idx < 1024; idx += 256) {
            int kk = idx & 15, mn = idx >> 4;
            As[kk * SA + mn] = lab[(n0 + mn) * NKC + k0 + kk];
        }
        for (int idx = tid; idx < 1024; idx += 256) {
            int ln = idx & 63, kk = idx >> 6;   // M-fastest (l contiguous)
            Bs[kk * SA + ln] = g_k1[((size_t)b * NKC + k0 + kk) * LCP + l0 + ln];
        }
        __syncthreads();
        mm16(As, Bs, ty, tx, acc);
        __syncthreads();
    }
#pragma unroll
    for (int i = 0; i < 4; ++i) {
        int n = n0 + ty * 4 + i;
#pragma unroll
        for (int j = 0; j < 2; ++j) {
            float2 v = up2(acc[i][j]);
            int l = l0 + tx * 4 + j * 2;
            if (l < LC)     g_b2s[(size_t)(b * NLB + n) * LCP + l]     = v.x;
            if (l + 1 < LC) g_b2s[(size_t)(b * NLB + n) * LCP + l + 1] = v.y;
        }
    }
}

// ---------------- 8) out2[n][k] = sum_l P2[n][l] * V1[k][l]:  M=n, N=k, K=1022 ----------------
__global__ void out2_kernel() {
    int b = blockIdx.z, n0 = blockIdx.x * 64, kc0 = blockIdx.y * 64;
    __shared__ float As[16 * SA], Bs[16 * SA];
    int tid = threadIdx.x, tx = tid & 15, ty = tid >> 4;
    unsigned long long acc[4][2] = {};
    for (int lo = 0; lo < LCP; lo += 16) {
        for (int idx = tid; idx < 1024; idx += 256) {
            int kk = idx & 15, mn = idx >> 4;
            As[kk * SA + mn] = g_b2s[(size_t)(b * NLB + n0 + mn) * LCP + lo + kk];   // pads zero
            Bs[kk * SA + mn] = g_v1[((size_t)b * NKC + kc0 + mn) * LCP + lo + kk];   // pads zero
        }
        __syncthreads();
        mm16(As, Bs, ty, tx, acc);
        __syncthreads();
    }
#pragma unroll
    for (int i = 0; i < 4; ++i) {
        int n = n0 + ty * 4 + i;
#pragma unroll
        for (int j = 0; j < 2; ++j) {
            float2 v = up2(acc[i][j]);
            int k = kc0 + tx * 4 + j * 2;
            float* dst = g_o2 + ((size_t)(b * NLB + n) * NKC + k);
            dst[0] = v.x; dst[1] = v.y;
        }
    }
}

// ---------------- 9) l2norm + concat into d_out ----------------
__global__ void l2norm_kernel(float* __restrict__ out) {
    int row = blockIdx.x;                 // b*NL + n
    const float* src = ((blockIdx.y == 0) ? g_o1 : g_o2) + (size_t)row * NKC;
    int tid = threadIdx.x;                // 128
    float4 v = ((const float4*)src)[tid];
    float ss = v.x * v.x + v.y * v.y + v.z * v.z + v.w * v.w;
    __shared__ float red[128];
    red[tid] = ss; __syncthreads();
    for (int s = 64; s > 0; s >>= 1) { if (tid < s) red[tid] += red[tid + s]; __syncthreads(); }
    float inv = 1.f / fmaxf(sqrtf(red[0]), 1e-12f);
    float4 o = make_float4(v.x * inv, v.y * inv, v.z * inv, v.w * inv);
    ((float4*)(out + (size_t)row * 1024 + blockIdx.y * NKC))[tid] = o;
}

// ---------------- launch ----------------
extern "C" void kernel_launch(void* const* d_in, const int* in_sizes, int n_in,
                              void* d_out, int out_size) {
    (void)in_sizes; (void)n_in; (void)out_size;
    const float* emb = (const float*)d_in[0];
    const float* lab = (const float*)d_in[1];
    const float* wq  = (const float*)d_in[2];
    const float* bq  = (const float*)d_in[3];
    const float* wk  = (const float*)d_in[4];
    const float* bk  = (const float*)d_in[5];
    const float* wv  = (const float*)d_in[6];
    const float* bv  = (const float*)d_in[7];
    const float* w1  = (const float*)d_in[8];
    const float* w2  = (const float*)d_in[9];
    float* out = (float*)d_out;

    dim3 thr(256);
    conv_kernel<<<dim3(16, 8, 16), thr>>>(emb, wq, bq, 0);
    conv_kernel<<<dim3(16, 8, 16), thr>>>(emb, wk, bk, 1);
    conv_kernel<<<dim3(16, 8, 16), thr>>>(emb, wv, bv, 2);

    score_qk_kernel<<<dim3(16, 16, 128), thr>>>();
    softmax_kernel<<<dim3(1022, 128), thr>>>(0);
    attn_out_kernel<<<dim3(16, 1, 128), thr>>>();

    lsa1_kernel<<<dim3(16, 4, 16), thr>>>(w1);
    score2_kernel<<<dim3(16, 16, 16), thr>>>(w2);
    softmax_kernel<<<dim3(1024, 16), thr>>>(1);
    out1_kernel<<<dim3(16, 8, 16), thr>>>();

    b2_kernel<<<dim3(16, 16, 16), thr>>>(lab);
    softmax_kernel<<<dim3(1024, 16), thr>>>(2);
    out2_kernel<<<dim3(16, 8, 16), thr>>>();

    l2norm_kernel<<<dim3(16384, 2), dim3(128)>>>(out);
}

// round 2
// speedup vs baseline: 1.0019x; 1.0019x over previous
#include <cuda_runtime.h>

// Problem constants
#define BB   16
#define LSEQ 1024
#define DIN  512
#define NKC  512      // num kernels (channels)
#define HH   8        // heads
#define DHH  64       // dh = NKC/HH
#define LC   1022     // Lc = L - 2 (VALID conv, width 3)
#define LCP  1024     // padded Lc
#define NLB  1024     // num labels
#define ADIM 256      // attention dim
#define KCONV 1536    // 3*DIN
#define SA   66       // smem row stride (conflict-free both load orders, 8B aligned)

// ---------------- scratch (__device__ globals; zero-initialized at load; pads never written) ----------
__device__ float g_q1[BB * NKC * LCP];          // [B][NK][LCP]
__device__ float g_k1[BB * NKC * LCP];
__device__ float g_v1[BB * NKC * LCP];
__device__ float g_attn[128 * 1024 * 1024];     // [B*H][LCP][LCP]  (537 MB)
__device__ float g_c1[BB * LC * NKC];           // cnn_out1 [B][LC][NK]
__device__ float g_t1[BB * LC * ADIM];          // tanh(C1 @ W1^T)  [B][LC][AD]
__device__ float g_sc[BB * NLB * LCP];          // label-sum scores [B][NL][LCP]
__device__ float g_b2s[BB * NLB * LCP];         // cross-attn scores [B][NL][LCP]
__device__ float g_o1[BB * NLB * NKC];          // out1 pre-norm
__device__ float g_o2[BB * NLB * NKC];          // out2 pre-norm

// ---------------- packed f32x2 helpers ----------------
__device__ __forceinline__ unsigned long long pk2(float lo, float hi) {
    unsigned long long r;
    asm("mov.b64 %0, {%1, %2};" : "=l"(r) : "f"(lo), "f"(hi));
    return r;
}
__device__ __forceinline__ void fma2(unsigned long long& d, unsigned long long a, unsigned long long b) {
    asm("fma.rn.f32x2 %0, %1, %2, %0;" : "+l"(d) : "l"(a), "l"(b));
}
__device__ __forceinline__ float2 up2(unsigned long long v) {
    float lo, hi;
    asm("mov.b64 {%0, %1}, %2;" : "=f"(lo), "=f"(hi) : "l"(v));
    return make_float2(lo, hi);
}

// 64x64x16 tile microkernel: C[ty*4+i][tx*4 + j] accumulated in f32x2 pairs
__device__ __forceinline__ void mm16(const float* __restrict__ As, const float* __restrict__ Bs,
                                     int ty, int tx, unsigned long long (&acc)[4][2]) {
#pragma unroll
    for (int kk = 0; kk < 16; ++kk) {
        const float* ap = As + kk * SA + ty * 4;
        const float* bp = Bs + kk * SA + tx * 4;
        float2 a01 = *(const float2*)ap;
        float2 a23 = *(const float2*)(ap + 2);
        float2 b01 = *(const float2*)bp;
        float2 b23 = *(const float2*)(bp + 2);
        unsigned long long bb0 = pk2(b01.x, b01.y);
        unsigned long long bb1 = pk2(b23.x, b23.y);
        unsigned long long aa;
        aa = pk2(a01.x, a01.x); fma2(acc[0][0], aa, bb0); fma2(acc[0][1], aa, bb1);
        aa = pk2(a01.y, a01.y); fma2(acc[1][0], aa, bb0); fma2(acc[1][1], aa, bb1);
        aa = pk2(a23.x, a23.x); fma2(acc[2][0], aa, bb0); fma2(acc[2][1], aa, bb1);
        aa = pk2(a23.y, a23.y); fma2(acc[3][0], aa, bb0); fma2(acc[3][1], aa, bb1);
    }
}

// ---------------- 1) conv1d (width 3, VALID) + bias + elu ----------------
// C[o][l] = sum_{t,i} emb[b][l+t][i] * w[o][i][t];  M=o, N=l, K=1536
__global__ void conv_kernel(const float* __restrict__ emb, const float* __restrict__ w,
                            const float* __restrict__ bias, int which) {
    float* out = (which == 0) ? g_q1 : (which == 1) ? g_k1 : g_v1;
    int b = blockIdx.z, o0 = blockIdx.y * 64, l0 = blockIdx.x * 64;
    __shared__ float As[16 * SA], Bs[16 * SA];
    int tid = threadIdx.x, tx = tid & 15, ty = tid >> 4;
    unsigned long long acc[4][2] = {};
    for (int ko = 0; ko < KCONV; ko += 16) {
        int t = ko >> 9, i0 = ko & 511;
        for (int idx = tid; idx < 1024; idx += 256) {
            int kk = idx & 15, mn = idx >> 4;
            As[kk * SA + mn] = w[(o0 + mn) * KCONV + (i0 + kk) * 3 + t];
            int row = l0 + mn + t;
            Bs[kk * SA + mn] = (row < LSEQ) ? emb[((size_t)b * LSEQ + row) * DIN + i0 + kk] : 0.f;
        }
        __syncthreads();
        mm16(As, Bs, ty, tx, acc);
        __syncthreads();
    }
#pragma unroll
    for (int i = 0; i < 4; ++i) {
        int o = o0 + ty * 4 + i;
        float bv = bias[o];
#pragma unroll
        for (int j = 0; j < 2; ++j) {
            float2 v = up2(acc[i][j]);
            int l = l0 + tx * 4 + j * 2;
            float x0 = v.x + bv, x1 = v.y + bv;
            x0 = x0 > 0.f ? x0 : (__expf(x0) - 1.f);
            x1 = x1 > 0.f ? x1 : (__expf(x1) - 1.f);
            if (l < LC)     out[((size_t)b * NKC + o) * LCP + l]     = x0;
            if (l + 1 < LC) out[((size_t)b * NKC + o) * LCP + l + 1] = x1;
        }
    }
}

// ---------------- 2) self-attention scores A[l][m] = (Q^T K)/8 ----------------
__global__ void score_qk_kernel() {
    int z = blockIdx.z, b = z >> 3, h = z & 7;
    int l0 = blockIdx.x * 64, m0 = blockIdx.y * 64;
    const float* qb = g_q1 + ((size_t)b * NKC + h * DHH) * LCP;
    const float* kb = g_k1 + ((size_t)b * NKC + h * DHH) * LCP;
    __shared__ float As[16 * SA], Bs[16 * SA];
    int tid = threadIdx.x, tx = tid & 15, ty = tid >> 4;
    unsigned long long acc[4][2] = {};
    for (int k0 = 0; k0 < DHH; k0 += 16) {
        for (int idx = tid; idx < 1024; idx += 256) {
            int mn = idx & 63, kk = idx >> 6;   // M-fastest (l contiguous in gmem)
            As[kk * SA + mn] = qb[(k0 + kk) * LCP + l0 + mn];
            Bs[kk * SA + mn] = kb[(k0 + kk) * LCP + m0 + mn];
        }
        __syncthreads();
        mm16(As, Bs, ty, tx, acc);
        __syncthreads();
    }
    float* cbase = g_attn + (size_t)z * LCP * LCP;
#pragma unroll
    for (int i = 0; i < 4; ++i) {
        int l = l0 + ty * 4 + i;
        if (l >= LC) continue;
#pragma unroll
        for (int j = 0; j < 2; ++j) {
            float2 v = up2(acc[i][j]);
            int c = m0 + tx * 4 + j * 2;
            if (c < LC)     cbase[(size_t)l * LCP + c]     = v.x * 0.125f;
            if (c + 1 < LC) cbase[(size_t)l * LCP + c + 1] = v.y * 0.125f;
        }
    }
}

// ---------------- softmax over rows of length 1022 (stride 1024) ----------------
__global__ void softmax_kernel(int sel) {
    float* base = (sel == 0) ? g_attn : (sel == 1) ? g_sc : g_b2s;
    float* row = base + ((size_t)blockIdx.y * 1024 + blockIdx.x) * 1024;
    int tid = threadIdx.x;
    float v[4];
    float mx = -1e30f;
#pragma unroll
    for (int j = 0; j < 4; ++j) {
        int idx = tid + j * 256;
        v[j] = (idx < LC) ? row[idx] : -1e30f;
        mx = fmaxf(mx, v[j]);
    }
    __shared__ float red[256];
    red[tid] = mx; __syncthreads();
    for (int s = 128; s > 0; s >>= 1) { if (tid < s) red[tid] = fmaxf(red[tid], red[tid + s]); __syncthreads(); }
    mx = red[0]; __syncthreads();
    float sum = 0.f;
#pragma unroll
    for (int j = 0; j < 4; ++j) {
        int idx = tid + j * 256;
        v[j] = (idx < LC) ? __expf(v[j] - mx) : 0.f;
        sum += v[j];
    }
    red[tid] = sum; __syncthreads();
    for (int s = 128; s > 0; s >>= 1) { if (tid < s) red[tid] += red[tid + s]; __syncthreads(); }
    float inv = 1.f / red[0];
#pragma unroll
    for (int j = 0; j < 4; ++j) {
        int idx = tid + j * 256;
        if (idx < LC) row[idx] = v[j] * inv;
    }
}

// ---------------- 3) attention output -> cnn_out1[b][l][h*64+d] ----------------
// C[l][d] = sum_m P[l][m] * V[d][m];  M=l, N=d(64), K=1022(pad 1024, pads are zero)
__global__ void attn_out_kernel() {
    int z = blockIdx.z, b = z >> 3, h = z & 7;
    int l0 = blockIdx.x * 64;
    const float* prow = g_attn + (size_t)z * LCP * LCP;
    const float* vb = g_v1 + ((size_t)b * NKC + h * DHH) * LCP;
    __shared__ float As[16 * SA], Bs[16 * SA];
    int tid = threadIdx.x, tx = tid & 15, ty = tid >> 4;
    unsigned long long acc[4][2] = {};
    for (int m0 = 0; m0 < LCP; m0 += 16) {
        for (int idx = tid; idx < 1024; idx += 256) {
            int kk = idx & 15, mn = idx >> 4;   // K-fastest (m contiguous)
            As[kk * SA + mn] = prow[(size_t)(l0 + mn) * LCP + m0 + kk];
            Bs[kk * SA + mn] = vb[(size_t)mn * LCP + m0 + kk];
        }
        __syncthreads();
        mm16(As, Bs, ty, tx, acc);
        __syncthreads();
    }
#pragma unroll
    for (int i = 0; i < 4; ++i) {
        int l = l0 + ty * 4 + i;
        if (l >= LC) continue;
#pragma unroll
        for (int j = 0; j < 2; ++j) {
            float2 v = up2(acc[i][j]);
            int d = tx * 4 + j * 2;
            float* dst = g_c1 + ((size_t)(b * LC + l) * NKC + h * DHH + d);
            dst[0] = v.x; dst[1] = v.y;
        }
    }
}

// ---------------- 4) t1 = tanh(C1 @ W1^T):  M=l, N=a(256), K=512 ----------------
__global__ void lsa1_kernel(const float* __restrict__ w1) {
    int b = blockIdx.z, l0 = blockIdx.x * 64, a0 = blockIdx.y * 64;
    __shared__ float As[16 * SA], Bs[16 * SA];
    int tid = threadIdx.x, tx = tid & 15, ty = tid >> 4;
    unsigned long long acc[4][2] = {};
    for (int k0 = 0; k0 < NKC; k0 += 16) {
        for (int idx = tid; idx < 1024; idx += 256) {
            int kk = idx & 15, mn = idx >> 4;
            int row = l0 + mn;
            As[kk * SA + mn] = (row < LC) ? g_c1[(size_t)(b * LC + row) * NKC + k0 + kk] : 0.f;
            Bs[kk * SA + mn] = w1[(a0 + mn) * NKC + k0 + kk];
        }
        __syncthreads();
        mm16(As, Bs, ty, tx, acc);
        __syncthreads();
    }
#pragma unroll
    for (int i = 0; i < 4; ++i) {
        int l = l0 + ty * 4 + i;
        if (l >= LC) continue;
#pragma unroll
        for (int j = 0; j < 2; ++j) {
            float2 v = up2(acc[i][j]);
            int a = a0 + tx * 4 + j * 2;
            float* dst = g_t1 + ((size_t)(b * LC + l) * ADIM + a);
            dst[0] = tanhf(v.x); dst[1] = tanhf(v.y);
        }
    }
}

// ---------------- 5) score[n][l] = sum_a W2[n][a] * t1[l][a]:  M=n, N=l, K=256 ----------------
__global__ void score2_kernel(const float* __restrict__ w2) {
    int b = blockIdx.z, n0 = blockIdx.x * 64, l0 = blockIdx.y * 64;
    __shared__ float As[16 * SA], Bs[16 * SA];
    int tid = threadIdx.x, tx = tid & 15, ty = tid >> 4;
    unsigned long long acc[4][2] = {};
    for (int k0 = 0; k0 < ADIM; k0 += 16) {
        for (int idx = tid; idx < 1024; idx += 256) {
            int kk = idx & 15, mn = idx >> 4;
            As[kk * SA + mn] = w2[(n0 + mn) * ADIM + k0 + kk];
            int row = l0 + mn;
            Bs[kk * SA + mn] = (row < LC) ? g_t1[(size_t)(b * LC + row) * ADIM + k0 + kk] : 0.f;
        }
        __syncthreads();
        mm16(As, Bs, ty, tx, acc);
        __syncthreads();
    }
#pragma unroll
    for (int i = 0; i < 4; ++i) {
        int n = n0 + ty * 4 + i;
#pragma unroll
        for (int j = 0; j < 2; ++j) {
            float2 v = up2(acc[i][j]);
            int l = l0 + tx * 4 + j * 2;
            if (l < LC)     g_sc[(size_t)(b * NLB + n) * LCP + l]     = v.x;
            if (l + 1 < LC) g_sc[(size_t)(b * NLB + n) * LCP + l + 1] = v.y;
        }
    }
}

// ---------------- 6) out1[n][k] = sum_l P[n][l] * C1[l][k]:  M=n, N=k, K=1022 ----------------
__global__ void out1_kernel() {
    int b = blockIdx.z, n0 = blockIdx.x * 64, kc0 = blockIdx.y * 64;
    __shared__ float As[16 * SA], Bs[16 * SA];
    int tid = threadIdx.x, tx = tid & 15, ty = tid >> 4;
    unsigned long long acc[4][2] = {};
    for (int ko = 0; ko < LCP; ko += 16) {
        for (int idx = tid; idx < 1024; idx += 256) {
            int kk = idx & 15, mn = idx >> 4;
            As[kk * SA + mn] = g_sc[(size_t)(b * NLB + n0 + mn) * LCP + ko + kk];  // pads zero
        }
        for (int idx = tid; idx < 1024; idx += 256) {
            int nn = idx & 63, kk = idx >> 6;   // M-fastest (k contiguous)
            int row = ko + kk;
            Bs[kk * SA + nn] = (row < LC) ? g_c1[(size_t)(b * LC + row) * NKC + kc0 + nn] : 0.f;
        }
        __syncthreads();
        mm16(As, Bs, ty, tx, acc);
        __syncthreads();
    }
#pragma unroll
    for (int i = 0; i < 4; ++i) {
        int n = n0 + ty * 4 + i;
#pragma unroll
        for (int j = 0; j < 2; ++j) {
            float2 v = up2(acc[i][j]);
            int k = kc0 + tx * 4 + j * 2;
            float* dst = g_o1 + ((size_t)(b * NLB + n) * NKC + k);
            dst[0] = v.x; dst[1] = v.y;
        }
    }
}

// ---------------- 7) b2[n][l] = sum_k LE[n][k] * K1[k][l]:  M=n, N=l, K=512 ----------------
__global__ void b2_kernel(const float* __restrict__ lab) {
    int b = blockIdx.z, n0 = blockIdx.x * 64, l0 = blockIdx.y * 64;
    __shared__ float As[16 * SA], Bs[16 * SA];
    int tid = threadIdx.x, tx = tid & 15, ty = tid >> 4;
    unsigned long long acc[4][2] = {};
    for (int k0 = 0; k0 < NKC; k0 += 16) {
        for (int idx = tid; idx < 1024; idx += 256) {
            int kk = idx & 15, mn = idx >> 4;
            As[kk * SA + mn] = lab[(n0 + mn) * NKC + k0 + kk];
        }
        for (int idx = tid; idx < 1024; idx += 256) {
            int ln = idx & 63, kk = idx >> 6;   // M-fastest (l contiguous)
            Bs[kk * SA + ln] = g_k1[((size_t)b * NKC + k0 + kk) * LCP + l0 + ln];
        }
        __syncthreads();
        mm16(As, Bs, ty, tx, acc);
        __syncthreads();
    }
#pragma unroll
    for (int i = 0; i < 4; ++i) {
        int n = n0 + ty * 4 + i;
#pragma unroll
        for (int j = 0; j < 2; ++j) {
            float2 v = up2(acc[i][j]);
            int l = l0 + tx * 4 + j * 2;
            if (l < LC)     g_b2s[(size_t)(b * NLB + n) * LCP + l]     = v.x;
            if (l + 1 < LC) g_b2s[(size_t)(b * NLB + n) * LCP + l + 1] = v.y;
        }
    }
}

// ---------------- 8) out2[n][k] = sum_l P2[n][l] * V1[k][l]:  M=n, N=k, K=1022 ----------------
__global__ void out2_kernel() {
    int b = blockIdx.z, n0 = blockIdx.x * 64, kc0 = blockIdx.y * 64;
    __shared__ float As[16 * SA], Bs[16 * SA];
    int tid = threadIdx.x, tx = tid & 15, ty = tid >> 4;
    unsigned long long acc[4][2] = {};
    for (int lo = 0; lo < LCP; lo += 16) {
        for (int idx = tid; idx < 1024; idx += 256) {
            int kk = idx & 15, mn = idx >> 4;
            As[kk * SA + mn] = g_b2s[(size_t)(b * NLB + n0 + mn) * LCP + lo + kk];   // pads zero
            Bs[kk * SA + mn] = g_v1[((size_t)b * NKC + kc0 + mn) * LCP + lo + kk];   // pads zero
        }
        __syncthreads();
        mm16(As, Bs, ty, tx, acc);
        __syncthreads();
    }
#pragma unroll
    for (int i = 0; i < 4; ++i) {
        int n = n0 + ty * 4 + i;
#pragma unroll
        for (int j = 0; j < 2; ++j) {
            float2 v = up2(acc[i][j]);
            int k = kc0 + tx * 4 + j * 2;
            float* dst = g_o2 + ((size_t)(b * NLB + n) * NKC + k);
            dst[0] = v.x; dst[1] = v.y;
        }
    }
}

// ---------------- 9) l2norm + concat into d_out ----------------
__global__ void l2norm_kernel(float* __restrict__ out) {
    int row = blockIdx.x;                 // b*NL + n
    const float* src = ((blockIdx.y == 0) ? g_o1 : g_o2) + (size_t)row * NKC;
    int tid = threadIdx.x;                // 128
    float4 v = ((const float4*)src)[tid];
    float ss = v.x * v.x + v.y * v.y + v.z * v.z + v.w * v.w;
    __shared__ float red[128];
    red[tid] = ss; __syncthreads();
    for (int s = 64; s > 0; s >>= 1) { if (tid < s) red[tid] += red[tid + s]; __syncthreads(); }
    float inv = 1.f / fmaxf(sqrtf(red[0]), 1e-12f);
    float4 o = make_float4(v.x * inv, v.y * inv, v.z * inv, v.w * inv);
    ((float4*)(out + (size_t)row * 1024 + blockIdx.y * NKC))[tid] = o;
}

// ---------------- launch ----------------
extern "C" void kernel_launch(void* const* d_in, const int* in_sizes, int n_in,
                              void* d_out, int out_size) {
    (void)in_sizes; (void)n_in; (void)out_size;
    const float* emb = (const float*)d_in[0];
    const float* lab = (const float*)d_in[1];
    const float* wq  = (const float*)d_in[2];
    const float* bq  = (const float*)d_in[3];
    const float* wk  = (const float*)d_in[4];
    const float* bk  = (const float*)d_in[5];
    const float* wv  = (const float*)d_in[6];
    const float* bv  = (const float*)d_in[7];
    const float* w1  = (const float*)d_in[8];
    const float* w2  = (const float*)d_in[9];
    float* out = (float*)d_out;

    dim3 thr(256);
    conv_kernel<<<dim3(16, 8, 16), thr>>>(emb, wq, bq, 0);
    conv_kernel<<<dim3(16, 8, 16), thr>>>(emb, wk, bk, 1);
    conv_kernel<<<dim3(16, 8, 16), thr>>>(emb, wv, bv, 2);

    score_qk_kernel<<<dim3(16, 16, 128), thr>>>();
    softmax_kernel<<<dim3(1022, 128), thr>>>(0);
    attn_out_kernel<<<dim3(16, 1, 128), thr>>>();

    lsa1_kernel<<<dim3(16, 4, 16), thr>>>(w1);
    score2_kernel<<<dim3(16, 16, 16), thr>>>(w2);
    softmax_kernel<<<dim3(1024, 16), thr>>>(1);
    out1_kernel<<<dim3(16, 8, 16), thr>>>();

    b2_kernel<<<dim3(16, 16, 16), thr>>>(lab);
    softmax_kernel<<<dim3(1024, 16), thr>>>(2);
    out2_kernel<<<dim3(16, 8, 16), thr>>>();

    l2norm_kernel<<<dim3(16384, 2), dim3(128)>>>(out);
}

// round 4
// speedup vs baseline: 2.2091x; 2.2049x over previous
#include <cuda_runtime.h>
#include <cuda_bf16.h>
#include <cstdint>

#define BB    16
#define LSEQ  1024
#define DIN   512
#define NKC   512
#define HH    8
#define DHH   64
#define LC    1022
#define LCP   1024
#define NLB   1024
#define ADIM  256

// ---------- scratch (zero-init; pads never written) ----------
__device__ float g_q1[BB * NKC * LCP];
__device__ float g_k1[BB * NKC * LCP];
__device__ float g_v1[BB * NKC * LCP];
__device__ float g_attn[(size_t)128 * 1024 * 1024];
__device__ float g_c1[BB * LC * NKC];
__device__ float g_t1[BB * LC * ADIM];
__device__ float g_sc[BB * NLB * LCP];
__device__ float g_b2s[BB * NLB * LCP];
__device__ float g_o1[BB * NLB * NKC];
__device__ float g_o2[BB * NLB * NKC];
__device__ float g_wrep[3 * NKC * DIN];

// ---------- smem: per buffer AH(10240) AL(10240) BH(5120) BL(5120) = 30720; x2 ----------
#define AHOFF 0
#define ALOFF 10240
#define BHOFF 20480
#define BLOFF 25600
#define BUFB  30720
#define SMEMB (2 * BUFB)

__device__ __forceinline__ uint32_t s2u(const void* p) {
    uint32_t a;
    asm("{ .reg .u64 t; cvta.to.shared.u64 t, %1; cvt.u32.u64 %0, t; }" : "=r"(a) : "l"(p));
    return a;
}
__device__ __forceinline__ void ldm4(uint32_t* r, uint32_t addr) {
    asm volatile("ldmatrix.sync.aligned.m8n8.x4.shared.b16 {%0,%1,%2,%3}, [%4];"
                 : "=r"(r[0]), "=r"(r[1]), "=r"(r[2]), "=r"(r[3]) : "r"(addr));
}
__device__ __forceinline__ void mma16816(float* c, const uint32_t* a, const uint32_t* b) {
    asm volatile("mma.sync.aligned.m16n8k16.row.col.f32.bf16.bf16.f32 "
                 "{%0,%1,%2,%3}, {%4,%5,%6,%7}, {%8,%9}, {%0,%1,%2,%3};"
                 : "+f"(c[0]), "+f"(c[1]), "+f"(c[2]), "+f"(c[3])
                 : "r"(a[0]), "r"(a[1]), "r"(a[2]), "r"(a[3]), "r"(b[0]), "r"(b[1]));
}

__device__ __forceinline__ uint32_t bfu(__nv_bfloat162 v) { return *reinterpret_cast<uint32_t*>(&v); }
__device__ __forceinline__ void cvt4(float4 v, uint2& hi, uint2& lo) {
    __nv_bfloat162 h01 = __floats2bfloat162_rn(v.x, v.y);
    __nv_bfloat162 h23 = __floats2bfloat162_rn(v.z, v.w);
    float2 f01 = __bfloat1622float2(h01), f23 = __bfloat1622float2(h23);
    __nv_bfloat162 l01 = __floats2bfloat162_rn(v.x - f01.x, v.y - f01.y);
    __nv_bfloat162 l23 = __floats2bfloat162_rn(v.z - f23.x, v.w - f23.y);
    hi = make_uint2(bfu(h01), bfu(h23));
    lo = make_uint2(bfu(l01), bfu(l23));
}
__device__ __forceinline__ void st1hl(char* hibase, float x, int elem) {
    __nv_bfloat16 h = __float2bfloat16(x);
    __nv_bfloat16 l = __float2bfloat16(x - __bfloat162float(h));
    *(__nv_bfloat16*)(hibase + elem * 2) = h;
    *(__nv_bfloat16*)(hibase + ALOFF - AHOFF + elem * 2) = l;   // lo at +10240 (A) — caller adjusts for B
}

// per-stage config
template <int STG> struct Cfg {
    static constexpr int  NCH = (STG <= 2) ? 48 : (STG == 3) ? 2 : (STG == 4) ? 32 :
                                (STG == 5) ? 16 : (STG == 6) ? 8 : (STG == 7) ? 32 :
                                (STG == 8) ? 16 : 32;
    static constexpr bool TRA = (STG == 3);
    static constexpr bool TRB = (STG == 3) || (STG == 7) || (STG == 8);
};

template <int STG>
__global__ void __launch_bounds__(256) gtc(const float* __restrict__ p0,
                                           const float* __restrict__ p2) {
    extern __shared__ __align__(128) char smem[];
    int tid = threadIdx.x, lane = tid & 31, wid = tid >> 5;
    int bx = blockIdx.x, by = blockIdx.y, z = blockIdx.z;
    int bb = z >> 3, hh = z & 7;

    float4 va[4], vb4[2];

    // ---- gather (registers) ----
    auto gather = [&](int c) {
        const float* Ab = nullptr;
        long SA_ = 0;
        int vrA = 128;
        if constexpr (STG <= 2) {
            int t3 = c >> 4, i0 = (c & 15) * 32;
            Ab = g_wrep + ((size_t)t3 * NKC + bx * 128) * DIN + i0; SA_ = DIN;
        } else if constexpr (STG == 3) {
            Ab = g_q1 + ((size_t)(bb * NKC + hh * DHH + c * 32)) * LCP + bx * 128; SA_ = LCP;
        } else if constexpr (STG == 4) {
            Ab = g_attn + (size_t)z * LCP * LCP + (size_t)(bx * 128) * LCP + c * 32; SA_ = LCP;
        } else if constexpr (STG == 5) {
            Ab = g_c1 + ((size_t)z * LC + bx * 128) * NKC + c * 32; SA_ = NKC;
            int v = LC - bx * 128; vrA = v > 128 ? 128 : v;
        } else if constexpr (STG == 6) {
            Ab = p0 + (size_t)(bx * 128) * ADIM + c * 32; SA_ = ADIM;
        } else if constexpr (STG == 7) {
            Ab = g_sc + ((size_t)z * NLB + bx * 128) * LCP + c * 32; SA_ = LCP;
        } else if constexpr (STG == 8) {
            Ab = p0 + (size_t)(bx * 128) * NKC + c * 32; SA_ = NKC;
        } else {
            Ab = g_b2s + ((size_t)z * NLB + bx * 128) * LCP + c * 32; SA_ = LCP;
        }
        if constexpr (Cfg<STG>::TRA) {
            int kk = tid >> 3, m0 = (tid & 7) * 16;
            const float* p = Ab + (long)kk * SA_ + m0;
#pragma unroll
            for (int j = 0; j < 4; ++j) va[j] = *(const float4*)(p + j * 4);
        } else {
            int r = tid >> 1, cq = (tid & 1) * 16;
            bool ok = r < vrA;
            const float* p = Ab + (long)r * SA_ + cq;
#pragma unroll
            for (int j = 0; j < 4; ++j)
                va[j] = ok ? *(const float4*)(p + j * 4) : make_float4(0.f, 0.f, 0.f, 0.f);
        }

        const float* Bb = nullptr;
        long SB_ = 0;
        int vrB = 64, vbB = 32;
        if constexpr (STG <= 2) {
            int t3 = c >> 4, i0 = (c & 15) * 32;
            Bb = p0 + ((size_t)z * LSEQ + by * 64 + t3) * DIN + i0; SB_ = DIN;
            vrB = LSEQ - by * 64 - t3; if (vrB > 64) vrB = 64;
        } else if constexpr (STG == 3) {
            Bb = g_k1 + ((size_t)(bb * NKC + hh * DHH + c * 32)) * LCP + by * 64; SB_ = LCP;
        } else if constexpr (STG == 4) {
            Bb = g_v1 + ((size_t)bb * NKC + hh * DHH) * LCP + c * 32; SB_ = LCP;
        } else if constexpr (STG == 5) {
            Bb = p0 + (size_t)(by * 64) * NKC + c * 32; SB_ = NKC;
        } else if constexpr (STG == 6) {
            Bb = g_t1 + ((size_t)z * LC + by * 64) * ADIM + c * 32; SB_ = ADIM;
            int v = LC - by * 64; vrB = v > 64 ? 64 : v;
        } else if constexpr (STG == 7) {
            Bb = g_c1 + ((size_t)z * LC + c * 32) * NKC + by * 64; SB_ = NKC;
            int v = LC - c * 32; vbB = v > 32 ? 32 : v;
        } else if constexpr (STG == 8) {
            Bb = g_k1 + ((size_t)z * NKC + c * 32) * LCP + by * 64; SB_ = LCP;
        } else {
            Bb = g_v1 + ((size_t)z * NKC + by * 64) * LCP + c * 32; SB_ = LCP;
        }
        if constexpr (Cfg<STG>::TRB) {
            int kk = tid >> 3, n0 = (tid & 7) * 8;
            bool ok = kk < vbB;
            const float* p = Bb + (long)kk * SB_ + n0;
#pragma unroll
            for (int j = 0; j < 2; ++j)
                vb4[j] = ok ? *(const float4*)(p + j * 4) : make_float4(0.f, 0.f, 0.f, 0.f);
        } else {
            int r = tid >> 2, cq = (tid & 3) * 8;
            bool ok = r < vrB;
            const float* p = Bb + (long)r * SB_ + cq;
#pragma unroll
            for (int j = 0; j < 2; ++j)
                vb4[j] = ok ? *(const float4*)(p + j * 4) : make_float4(0.f, 0.f, 0.f, 0.f);
        }
    };

    // ---- stash (convert + STS) ----
    auto stash = [&](char* buf) {
        if constexpr (Cfg<STG>::TRA) {
            int kk = tid >> 3, m0 = (tid & 7) * 16;
#pragma unroll
            for (int j = 0; j < 4; ++j) {
                const float* fv = (const float*)&va[j];
#pragma unroll
                for (int e = 0; e < 4; ++e)
                    st1hl(buf + AHOFF, fv[e], (m0 + 4 * j + e) * 40 + kk);
            }
        } else {
            int r = tid >> 1, cq = (tid & 1) * 16;
#pragma unroll
            for (int j = 0; j < 4; ++j) {
                uint2 hi, lo;
                cvt4(va[j], hi, lo);
                int el = r * 40 + cq + 4 * j;
                *(uint2*)(buf + AHOFF + el * 2) = hi;
                *(uint2*)(buf + ALOFF + el * 2) = lo;
            }
        }
        if constexpr (Cfg<STG>::TRB) {
            int kk = tid >> 3, n0 = (tid & 7) * 8;
#pragma unroll
            for (int j = 0; j < 2; ++j) {
                const float* fv = (const float*)&vb4[j];
#pragma unroll
                for (int e = 0; e < 4; ++e) {
                    float x = fv[e];
                    int el = (n0 + 4 * j + e) * 40 + kk;
                    __nv_bfloat16 h = __float2bfloat16(x);
                    __nv_bfloat16 l = __float2bfloat16(x - __bfloat162float(h));
                    *(__nv_bfloat16*)(buf + BHOFF + el * 2) = h;
                    *(__nv_bfloat16*)(buf + BLOFF + el * 2) = l;
                }
            }
        } else {
            int r = tid >> 2, cq = (tid & 3) * 8;
#pragma unroll
            for (int j = 0; j < 2; ++j) {
                uint2 hi, lo;
                cvt4(vb4[j], hi, lo);
                int el = r * 40 + cq + 4 * j;
                *(uint2*)(buf + BHOFF + el * 2) = hi;
                *(uint2*)(buf + BLOFF + el * 2) = lo;
            }
        }
    };

    float acc[2][4][4];
#pragma unroll
    for (int a = 0; a < 2; ++a)
#pragma unroll
        for (int b2 = 0; b2 < 4; ++b2)
#pragma unroll
            for (int e = 0; e < 4; ++e) acc[a][b2][e] = 0.f;

    int warpM = wid & 3, warpN = wid >> 2;

    gather(0);
    for (int c = 0; c < Cfg<STG>::NCH; ++c) {
        char* buf = smem + (c & 1) * BUFB;
        stash(buf);
        __syncthreads();
        if (c + 1 < Cfg<STG>::NCH) gather(c + 1);

        uint32_t sA = s2u(buf + AHOFF);
        uint32_t sB = s2u(buf + BHOFF);
#pragma unroll
        for (int kb = 0; kb < 2; ++kb) {
            uint32_t ah[2][4], al[2][4];
#pragma unroll
            for (int mi = 0; mi < 2; ++mi) {
                uint32_t addr = sA + ((warpM * 32 + mi * 16 + (lane & 15)) * 40 +
                                      kb * 16 + (lane >> 4) * 8) * 2;
                ldm4(ah[mi], addr);
                ldm4(al[mi], addr + (ALOFF - AHOFF));
            }
            uint32_t bh[2][4], bl[2][4];
#pragma unroll
            for (int g = 0; g < 2; ++g) {
                uint32_t addr = sB + ((warpN * 32 + g * 16 + (lane & 7) + ((lane >> 4) & 1) * 8) * 40 +
                                      kb * 16 + ((lane >> 3) & 1) * 8) * 2;
                ldm4(bh[g], addr);
                ldm4(bl[g], addr + (BLOFF - BHOFF));
            }
#pragma unroll
            for (int mi = 0; mi < 2; ++mi)
#pragma unroll
                for (int ni = 0; ni < 4; ++ni) {
                    const uint32_t* bhf = &bh[ni >> 1][(ni & 1) * 2];
                    const uint32_t* blf = &bl[ni >> 1][(ni & 1) * 2];
                    mma16816(acc[mi][ni], ah[mi], bhf);
                    mma16816(acc[mi][ni], ah[mi], blf);
                    mma16816(acc[mi][ni], al[mi], bhf);
                }
        }
        __syncthreads();
    }

    // ---- epilogue: fragment -> gmem ----
    int r0 = lane >> 2, c0 = (lane & 3) * 2;
#pragma unroll
    for (int mi = 0; mi < 2; ++mi)
#pragma unroll
        for (int rh = 0; rh < 2; ++rh) {
            int m = warpM * 32 + mi * 16 + r0 + rh * 8;
            float* dst = nullptr;
            bool ok = true;
            int vmax = 64;
            float bias = 0.f;
            if constexpr (STG <= 2) {
                float* outp = (STG == 0) ? g_q1 : (STG == 1) ? g_k1 : g_v1;
                dst = outp + ((size_t)z * NKC + bx * 128 + m) * LCP + by * 64;
                int v = LC - by * 64; vmax = v > 64 ? 64 : v;
                bias = p2[bx * 128 + m];
            } else if constexpr (STG == 3) {
                int l = bx * 128 + m; ok = l < LC;
                dst = g_attn + (size_t)z * LCP * LCP + (size_t)l * LCP + by * 64;
                int v = LC - by * 64; vmax = v > 64 ? 64 : v;
            } else if constexpr (STG == 4) {
                int l = bx * 128 + m; ok = l < LC;
                dst = g_c1 + ((size_t)bb * LC + l) * NKC + hh * DHH;
            } else if constexpr (STG == 5) {
                int l = bx * 128 + m; ok = l < LC;
                dst = g_t1 + ((size_t)z * LC + l) * ADIM + by * 64;
            } else if constexpr (STG == 6) {
                dst = g_sc + ((size_t)z * NLB + bx * 128 + m) * LCP + by * 64;
                int v = LC - by * 64; vmax = v > 64 ? 64 : v;
            } else if constexpr (STG == 7) {
                dst = g_o1 + ((size_t)z * NLB + bx * 128 + m) * NKC + by * 64;
            } else if constexpr (STG == 8) {
                dst = g_b2s + ((size_t)z * NLB + bx * 128 + m) * LCP + by * 64;
                int v = LC - by * 64; vmax = v > 64 ? 64 : v;
            } else {
                dst = g_o2 + ((size_t)z * NLB + bx * 128 + m) * NKC + by * 64;
            }
            if (!ok) continue;
#pragma unroll
            for (int ni = 0; ni < 4; ++ni) {
                int col = warpN * 32 + ni * 8 + c0;
                if (col < vmax) {
                    float v0 = acc[mi][ni][rh * 2 + 0];
                    float v1 = acc[mi][ni][rh * 2 + 1];
                    if constexpr (STG <= 2) {
                        v0 += bias; v1 += bias;
                        v0 = v0 > 0.f ? v0 : (__expf(v0) - 1.f);
                        v1 = v1 > 0.f ? v1 : (__expf(v1) - 1.f);
                    }
                    if constexpr (STG == 3) { v0 *= 0.125f; v1 *= 0.125f; }
                    if constexpr (STG == 5) { v0 = tanhf(v0); v1 = tanhf(v1); }
                    *(float2*)(dst + col) = make_float2(v0, v1);
                }
            }
        }
}

// ---------- weight repack: g_wrep[t][o][i] = w[o][i][t] ----------
__global__ void repack_w(const float* __restrict__ w) {
    int idx = blockIdx.x * 256 + threadIdx.x;
    if (idx < NKC * DIN) {
        g_wrep[idx]                 = w[idx * 3 + 0];
        g_wrep[NKC * DIN + idx]     = w[idx * 3 + 1];
        g_wrep[2 * NKC * DIN + idx] = w[idx * 3 + 2];
    }
}

// ---------- softmax over rows of length 1022 (stride 1024) ----------
__global__ void softmax_kernel(int sel) {
    float* base = (sel == 0) ? g_attn : (sel == 1) ? g_sc : g_b2s;
    float* row = base + ((size_t)blockIdx.y * 1024 + blockIdx.x) * 1024;
    int tid = threadIdx.x;
    float v[4];
    float mx = -1e30f;
#pragma unroll
    for (int j = 0; j < 4; ++j) {
        int idx = tid + j * 256;
        v[j] = (idx < LC) ? row[idx] : -1e30f;
        mx = fmaxf(mx, v[j]);
    }
    __shared__ float red[256];
    red[tid] = mx; __syncthreads();
    for (int s = 128; s > 0; s >>= 1) { if (tid < s) red[tid] = fmaxf(red[tid], red[tid + s]); __syncthreads(); }
    mx = red[0]; __syncthreads();
    float sum = 0.f;
#pragma unroll
    for (int j = 0; j < 4; ++j) {
        int idx = tid + j * 256;
        v[j] = (idx < LC) ? __expf(v[j] - mx) : 0.f;
        sum += v[j];
    }
    red[tid] = sum; __syncthreads();
    for (int s = 128; s > 0; s >>= 1) { if (tid < s) red[tid] += red[tid + s]; __syncthreads(); }
    float inv = 1.f / red[0];
#pragma unroll
    for (int j = 0; j < 4; ++j) {
        int idx = tid + j * 256;
        if (idx < LC) row[idx] = v[j] * inv;
    }
}

// ---------- l2norm + concat ----------
__global__ void l2norm_kernel(float* __restrict__ out) {
    int row = blockIdx.x;
    const float* src = ((blockIdx.y == 0) ? g_o1 : g_o2) + (size_t)row * NKC;
    int tid = threadIdx.x;
    float4 v = ((const float4*)src)[tid];
    float ss = v.x * v.x + v.y * v.y + v.z * v.z + v.w * v.w;
    __shared__ float red[128];
    red[tid] = ss; __syncthreads();
    for (int s = 64; s > 0; s >>= 1) { if (tid < s) red[tid] += red[tid + s]; __syncthreads(); }
    float inv = 1.f / fmaxf(sqrtf(red[0]), 1e-12f);
    ((float4*)(out + (size_t)row * 1024 + blockIdx.y * NKC))[tid] =
        make_float4(v.x * inv, v.y * inv, v.z * inv, v.w * inv);
}

// ---------- launch ----------
extern "C" void kernel_launch(void* const* d_in, const int* in_sizes, int n_in,
                              void* d_out, int out_size) {
    (void)in_sizes; (void)n_in; (void)out_size;
    const float* emb = (const float*)d_in[0];
    const float* lab = (const float*)d_in[1];
    const float* wq  = (const float*)d_in[2];
    const float* bq  = (const float*)d_in[3];
    const float* wk  = (const float*)d_in[4];
    const float* bk  = (const float*)d_in[5];
    const float* wv  = (const float*)d_in[6];
    const float* bv  = (const float*)d_in[7];
    const float* w1  = (const float*)d_in[8];
    const float* w2  = (const float*)d_in[9];
    float* out = (float*)d_out;

    cudaFuncSetAttribute(gtc<0>, cudaFuncAttributeMaxDynamicSharedMemorySize, SMEMB);
    cudaFuncSetAttribute(gtc<1>, cudaFuncAttributeMaxDynamicSharedMemorySize, SMEMB);
    cudaFuncSetAttribute(gtc<2>, cudaFuncAttributeMaxDynamicSharedMemorySize, SMEMB);
    cudaFuncSetAttribute(gtc<3>, cudaFuncAttributeMaxDynamicSharedMemorySize, SMEMB);
    cudaFuncSetAttribute(gtc<4>, cudaFuncAttributeMaxDynamicSharedMemorySize, SMEMB);
    cudaFuncSetAttribute(gtc<5>, cudaFuncAttributeMaxDynamicSharedMemorySize, SMEMB);
    cudaFuncSetAttribute(gtc<6>, cudaFuncAttributeMaxDynamicSharedMemorySize, SMEMB);
    cudaFuncSetAttribute(gtc<7>, cudaFuncAttributeMaxDynamicSharedMemorySize, SMEMB);
    cudaFuncSetAttribute(gtc<8>, cudaFuncAttributeMaxDynamicSharedMemorySize, SMEMB);
    cudaFuncSetAttribute(gtc<9>, cudaFuncAttributeMaxDynamicSharedMemorySize, SMEMB);

    dim3 thr(256);
    repack_w<<<1024, 256>>>(wq);
    gtc<0><<<dim3(4, 16, 16), thr, SMEMB>>>(emb, bq);
    repack_w<<<1024, 256>>>(wk);
    gtc<1><<<dim3(4, 16, 16), thr, SMEMB>>>(emb, bk);
    repack_w<<<1024, 256>>>(wv);
    gtc<2><<<dim3(4, 16, 16), thr, SMEMB>>>(emb, bv);

    gtc<3><<<dim3(8, 16, 128), thr, SMEMB>>>(nullptr, nullptr);
    softmax_kernel<<<dim3(1022, 128), thr>>>(0);
    gtc<4><<<dim3(8, 1, 128), thr, SMEMB>>>(nullptr, nullptr);

    gtc<5><<<dim3(8, 4, 16), thr, SMEMB>>>(w1, nullptr);
    gtc<6><<<dim3(8, 16, 16), thr, SMEMB>>>(w2, nullptr);
    softmax_kernel<<<dim3(1024, 16), thr>>>(1);
    gtc<7><<<dim3(8, 8, 16), thr, SMEMB>>>(nullptr, nullptr);

    gtc<8><<<dim3(8, 16, 16), thr, SMEMB>>>(lab, nullptr);
    softmax_kernel<<<dim3(1024, 16), thr>>>(2);
    gtc<9><<<dim3(8, 8, 16), thr, SMEMB>>>(nullptr, nullptr);

    l2norm_kernel<<<dim3(16384, 2), dim3(128)>>>(out);
}

// round 5
// speedup vs baseline: 2.8433x; 1.2871x over previous
#include <cuda_runtime.h>
#include <cuda_bf16.h>
#include <cstdint>

#define BB    16
#define LSEQ  1024
#define DIN   512
#define NKC   512
#define HH    8
#define DHH   64
#define LC    1022
#define LCP   1024
#define NLB   1024
#define ADIM  256

// ---------- scratch (zero-init; pads never written) ----------
__device__ float g_q1[BB * NKC * LCP];
__device__ float g_k1[BB * NKC * LCP];
__device__ float g_v1[BB * NKC * LCP];
__device__ float g_c1[BB * LC * NKC];
__device__ float g_t1[BB * LC * ADIM];
__device__ float g_sc[BB * NLB * LCP];
__device__ float g_b2s[BB * NLB * LCP];
__device__ float g_o1[BB * NLB * NKC];
__device__ float g_o2[BB * NLB * NKC];
__device__ float g_wrep[3 * NKC * DIN];

// ---------- gtc smem: per buffer AH(10240) AL(10240) BH(5120) BL(5120) ----------
#define AHOFF 0
#define ALOFF 10240
#define BHOFF 20480
#define BLOFF 25600
#define BUFB  30720
#define SMEMB (2 * BUFB)

__device__ __forceinline__ uint32_t s2u(const void* p) {
    uint32_t a;
    asm("{ .reg .u64 t; cvta.to.shared.u64 t, %1; cvt.u32.u64 %0, t; }" : "=r"(a) : "l"(p));
    return a;
}
__device__ __forceinline__ void ldm4(uint32_t* r, uint32_t addr) {
    asm volatile("ldmatrix.sync.aligned.m8n8.x4.shared.b16 {%0,%1,%2,%3}, [%4];"
                 : "=r"(r[0]), "=r"(r[1]), "=r"(r[2]), "=r"(r[3]) : "r"(addr));
}
__device__ __forceinline__ void mma16816(float* c, const uint32_t* a, const uint32_t* b) {
    asm volatile("mma.sync.aligned.m16n8k16.row.col.f32.bf16.bf16.f32 "
                 "{%0,%1,%2,%3}, {%4,%5,%6,%7}, {%8,%9}, {%0,%1,%2,%3};"
                 : "+f"(c[0]), "+f"(c[1]), "+f"(c[2]), "+f"(c[3])
                 : "r"(a[0]), "r"(a[1]), "r"(a[2]), "r"(a[3]), "r"(b[0]), "r"(b[1]));
}

__device__ __forceinline__ uint32_t bfu(__nv_bfloat162 v) { return *reinterpret_cast<uint32_t*>(&v); }
__device__ __forceinline__ uint32_t pkbf(float x, float y) {
    __nv_bfloat162 h = __floats2bfloat162_rn(x, y);
    return bfu(h);
}
__device__ __forceinline__ float lof(float x) {
    return x - __bfloat162float(__float2bfloat16(x));
}
__device__ __forceinline__ void cvt4(float4 v, uint2& hi, uint2& lo) {
    __nv_bfloat162 h01 = __floats2bfloat162_rn(v.x, v.y);
    __nv_bfloat162 h23 = __floats2bfloat162_rn(v.z, v.w);
    float2 f01 = __bfloat1622float2(h01), f23 = __bfloat1622float2(h23);
    __nv_bfloat162 l01 = __floats2bfloat162_rn(v.x - f01.x, v.y - f01.y);
    __nv_bfloat162 l23 = __floats2bfloat162_rn(v.z - f23.x, v.w - f23.y);
    hi = make_uint2(bfu(h01), bfu(h23));
    lo = make_uint2(bfu(l01), bfu(l23));
}

// ================= flash attention: fuses QK^T/8 -> softmax -> PV =================
// Q tile 128(l)x64(d) persistent; K/V streamed in 64-row chunks; warp owns 16 rows.
#define FSM 73728
__global__ void __launch_bounds__(256) flash_attn() {
    extern __shared__ __align__(128) char smem[];
    constexpr int QH = 0, QL = 18432, KH = 36864, KL = 46080, VH = 55296, VL = 64512;
    int tid = threadIdx.x, lane = tid & 31, w = tid >> 5;
    int l0 = blockIdx.x * 128, z = blockIdx.y, bb = z >> 3, hh = z & 7;
    const float* qb = g_q1 + ((size_t)(bb * NKC + hh * DHH)) * LCP;
    const float* kb = g_k1 + ((size_t)(bb * NKC + hh * DHH)) * LCP;
    const float* vb = g_v1 + ((size_t)(bb * NKC + hh * DHH)) * LCP;

    // Q transposed load: smem rows l (stride 72), cols d
    {
        int d = tid >> 2, lc = (tid & 3) * 32;
        const float* p = qb + (size_t)d * LCP + l0 + lc;
#pragma unroll
        for (int j = 0; j < 8; ++j) {
            float4 v = *(const float4*)(p + j * 4);
            const float* fv = (const float*)&v;
#pragma unroll
            for (int e = 0; e < 4; ++e) {
                int el = (lc + j * 4 + e) * 72 + d;
                __nv_bfloat16 h = __float2bfloat16(fv[e]);
                __nv_bfloat16 l = __float2bfloat16(fv[e] - __bfloat162float(h));
                *(__nv_bfloat16*)(smem + QH + el * 2) = h;
                *(__nv_bfloat16*)(smem + QL + el * 2) = l;
            }
        }
    }

    float OA[8][4];
#pragma unroll
    for (int i = 0; i < 8; ++i)
#pragma unroll
        for (int e = 0; e < 4; ++e) OA[i][e] = 0.f;
    float mrow0 = -1e30f, mrow1 = -1e30f, lrow0 = 0.f, lrow1 = 0.f;

    uint32_t sQh = s2u(smem + QH), sKh = s2u(smem + KH), sVh = s2u(smem + VH);

    for (int mt = 0; mt < 16; ++mt) {
        int m0 = mt * 64;
        __syncthreads();
        // K transposed: smem rows m, cols d
        {
            int d = tid >> 2, mc = (tid & 3) * 16;
            const float* p = kb + (size_t)d * LCP + m0 + mc;
#pragma unroll
            for (int j = 0; j < 4; ++j) {
                float4 v = *(const float4*)(p + j * 4);
                const float* fv = (const float*)&v;
#pragma unroll
                for (int e = 0; e < 4; ++e) {
                    int el = (mc + j * 4 + e) * 72 + d;
                    __nv_bfloat16 h = __float2bfloat16(fv[e]);
                    __nv_bfloat16 l = __float2bfloat16(fv[e] - __bfloat162float(h));
                    *(__nv_bfloat16*)(smem + KH + el * 2) = h;
                    *(__nv_bfloat16*)(smem + KL + el * 2) = l;
                }
            }
        }
        // V direct: smem rows d, cols m
        {
            int d = tid >> 2, mc = (tid & 3) * 16;
            const float* p = vb + (size_t)d * LCP + m0 + mc;
#pragma unroll
            for (int j = 0; j < 4; ++j) {
                float4 v = *(const float4*)(p + j * 4);
                uint2 hi, lo;
                cvt4(v, hi, lo);
                int el = d * 72 + mc + j * 4;
                *(uint2*)(smem + VH + el * 2) = hi;
                *(uint2*)(smem + VL + el * 2) = lo;
            }
        }
        __syncthreads();

        // ---- S = (Q K^T) ----
        float SA[8][4];
#pragma unroll
        for (int i = 0; i < 8; ++i)
#pragma unroll
            for (int e = 0; e < 4; ++e) SA[i][e] = 0.f;
#pragma unroll
        for (int kb_ = 0; kb_ < 4; ++kb_) {
            uint32_t ah[4], al_[4];
            uint32_t aaddr = sQh + ((w * 16 + (lane & 15)) * 72 + kb_ * 16 + (lane >> 4) * 8) * 2;
            ldm4(ah, aaddr);
            ldm4(al_, aaddr + (QL - QH));
#pragma unroll
            for (int g = 0; g < 4; ++g) {
                uint32_t bh_[4], bl_[4];
                uint32_t baddr = sKh + ((g * 16 + (lane & 7) + ((lane >> 4) & 1) * 8) * 72 +
                                        kb_ * 16 + ((lane >> 3) & 1) * 8) * 2;
                ldm4(bh_, baddr);
                ldm4(bl_, baddr + (KL - KH));
#pragma unroll
                for (int jj = 0; jj < 2; ++jj) {
                    int ni = g * 2 + jj;
                    mma16816(SA[ni], ah, &bh_[jj * 2]);
                    mma16816(SA[ni], ah, &bl_[jj * 2]);
                    mma16816(SA[ni], al_, &bh_[jj * 2]);
                }
            }
        }
        // scale 1/8 + mask invalid cols (only last m-tile: local cols 62,63)
#pragma unroll
        for (int ni = 0; ni < 8; ++ni) {
            SA[ni][0] *= 0.125f; SA[ni][1] *= 0.125f;
            SA[ni][2] *= 0.125f; SA[ni][3] *= 0.125f;
        }
        if (mt == 15 && (lane & 3) == 3) {
            SA[7][0] = SA[7][1] = SA[7][2] = SA[7][3] = -1e30f;
        }

        // ---- online softmax (rows gr, gr+8; quad-shfl reductions) ----
        float mc0 = -1e30f, mc1 = -1e30f;
#pragma unroll
        for (int ni = 0; ni < 8; ++ni) {
            mc0 = fmaxf(mc0, fmaxf(SA[ni][0], SA[ni][1]));
            mc1 = fmaxf(mc1, fmaxf(SA[ni][2], SA[ni][3]));
        }
        mc0 = fmaxf(mc0, __shfl_xor_sync(0xffffffffu, mc0, 1));
        mc0 = fmaxf(mc0, __shfl_xor_sync(0xffffffffu, mc0, 2));
        mc1 = fmaxf(mc1, __shfl_xor_sync(0xffffffffu, mc1, 1));
        mc1 = fmaxf(mc1, __shfl_xor_sync(0xffffffffu, mc1, 2));
        float mn0 = fmaxf(mrow0, mc0), mn1 = fmaxf(mrow1, mc1);
        float a0 = __expf(mrow0 - mn0), a1 = __expf(mrow1 - mn1);
        mrow0 = mn0; mrow1 = mn1;
        float s0 = 0.f, s1 = 0.f;
#pragma unroll
        for (int ni = 0; ni < 8; ++ni) {
            SA[ni][0] = __expf(SA[ni][0] - mn0); s0 += SA[ni][0];
            SA[ni][1] = __expf(SA[ni][1] - mn0); s0 += SA[ni][1];
            SA[ni][2] = __expf(SA[ni][2] - mn1); s1 += SA[ni][2];
            SA[ni][3] = __expf(SA[ni][3] - mn1); s1 += SA[ni][3];
        }
        s0 += __shfl_xor_sync(0xffffffffu, s0, 1);
        s0 += __shfl_xor_sync(0xffffffffu, s0, 2);
        s1 += __shfl_xor_sync(0xffffffffu, s1, 1);
        s1 += __shfl_xor_sync(0xffffffffu, s1, 2);
        lrow0 = lrow0 * a0 + s0;
        lrow1 = lrow1 * a1 + s1;
#pragma unroll
        for (int ni = 0; ni < 8; ++ni) {
            OA[ni][0] *= a0; OA[ni][1] *= a0;
            OA[ni][2] *= a1; OA[ni][3] *= a1;
        }

        // ---- O += P V : P repacked in-register to A fragments ----
#pragma unroll
        for (int t = 0; t < 4; ++t) {
            float p0 = SA[2 * t][0], p1 = SA[2 * t][1], p2 = SA[2 * t][2], p3 = SA[2 * t][3];
            float q0 = SA[2 * t + 1][0], q1 = SA[2 * t + 1][1], q2 = SA[2 * t + 1][2], q3 = SA[2 * t + 1][3];
            uint32_t aph[4], apl[4];
            aph[0] = pkbf(p0, p1); aph[1] = pkbf(p2, p3);
            aph[2] = pkbf(q0, q1); aph[3] = pkbf(q2, q3);
            apl[0] = pkbf(lof(p0), lof(p1)); apl[1] = pkbf(lof(p2), lof(p3));
            apl[2] = pkbf(lof(q0), lof(q1)); apl[3] = pkbf(lof(q2), lof(q3));
#pragma unroll
            for (int g = 0; g < 4; ++g) {
                uint32_t bh_[4], bl_[4];
                uint32_t baddr = sVh + ((g * 16 + (lane & 7) + ((lane >> 4) & 1) * 8) * 72 +
                                        t * 16 + ((lane >> 3) & 1) * 8) * 2;
                ldm4(bh_, baddr);
                ldm4(bl_, baddr + (VL - VH));
#pragma unroll
                for (int jj = 0; jj < 2; ++jj) {
                    int ni = g * 2 + jj;
                    mma16816(OA[ni], aph, &bh_[jj * 2]);
                    mma16816(OA[ni], aph, &bl_[jj * 2]);
                    mma16816(OA[ni], apl, &bh_[jj * 2]);
                }
            }
        }
    }

    // ---- epilogue ----
    float i0 = 1.f / lrow0, i1 = 1.f / lrow1;
    int gr = lane >> 2, cl = lane & 3;
    int la = l0 + w * 16 + gr, lb2 = la + 8;
#pragma unroll
    for (int ni = 0; ni < 8; ++ni) {
        int d = ni * 8 + cl * 2;
        if (la < LC)
            *(float2*)(g_c1 + ((size_t)bb * LC + la) * NKC + hh * DHH + d) =
                make_float2(OA[ni][0] * i0, OA[ni][1] * i0);
        if (lb2 < LC)
            *(float2*)(g_c1 + ((size_t)bb * LC + lb2) * NKC + hh * DHH + d) =
                make_float2(OA[ni][2] * i1, OA[ni][3] * i1);
    }
}

// ================= generic HMMA GEMM (stages 0-2, 5-9) =================
template <int STG> struct Cfg {
    static constexpr int  NCH = (STG <= 2) ? 48 : (STG == 5) ? 16 : (STG == 6) ? 8 :
                                (STG == 7) ? 32 : (STG == 8) ? 16 : 32;
    static constexpr bool TRB = (STG == 7) || (STG == 8);
};

template <int STG>
__global__ void __launch_bounds__(256) gtc(const float* __restrict__ p0,
                                           const float* __restrict__ p2) {
    extern __shared__ __align__(128) char smem[];
    int tid = threadIdx.x, lane = tid & 31, wid = tid >> 5;
    int bx = blockIdx.x, by = blockIdx.y, z = blockIdx.z;

    float4 va[4], vb4[2];

    auto gather = [&](int c) {
        const float* Ab = nullptr;
        long SA_ = 0;
        int vrA = 128;
        if constexpr (STG <= 2) {
            int t3 = c >> 4, i0 = (c & 15) * 32;
            Ab = g_wrep + ((size_t)t3 * NKC + bx * 128) * DIN + i0; SA_ = DIN;
        } else if constexpr (STG == 5) {
            Ab = g_c1 + ((size_t)z * LC + bx * 128) * NKC + c * 32; SA_ = NKC;
            int v = LC - bx * 128; vrA = v > 128 ? 128 : v;
        } else if constexpr (STG == 6) {
            Ab = p0 + (size_t)(bx * 128) * ADIM + c * 32; SA_ = ADIM;
        } else if constexpr (STG == 7) {
            Ab = g_sc + ((size_t)z * NLB + bx * 128) * LCP + c * 32; SA_ = LCP;
        } else if constexpr (STG == 8) {
            Ab = p0 + (size_t)(bx * 128) * NKC + c * 32; SA_ = NKC;
        } else {
            Ab = g_b2s + ((size_t)z * NLB + bx * 128) * LCP + c * 32; SA_ = LCP;
        }
        {
            int r = tid >> 1, cq = (tid & 1) * 16;
            bool ok = r < vrA;
            const float* p = Ab + (long)r * SA_ + cq;
#pragma unroll
            for (int j = 0; j < 4; ++j)
                va[j] = ok ? *(const float4*)(p + j * 4) : make_float4(0.f, 0.f, 0.f, 0.f);
        }

        const float* Bb = nullptr;
        long SB_ = 0;
        int vrB = 64, vbB = 32;
        if constexpr (STG <= 2) {
            int t3 = c >> 4, i0 = (c & 15) * 32;
            Bb = p0 + ((size_t)z * LSEQ + by * 64 + t3) * DIN + i0; SB_ = DIN;
            vrB = LSEQ - by * 64 - t3; if (vrB > 64) vrB = 64;
        } else if constexpr (STG == 5) {
            Bb = p0 + (size_t)(by * 64) * NKC + c * 32; SB_ = NKC;
        } else if constexpr (STG == 6) {
            Bb = g_t1 + ((size_t)z * LC + by * 64) * ADIM + c * 32; SB_ = ADIM;
            int v = LC - by * 64; vrB = v > 64 ? 64 : v;
        } else if constexpr (STG == 7) {
            Bb = g_c1 + ((size_t)z * LC + c * 32) * NKC + by * 64; SB_ = NKC;
            int v = LC - c * 32; vbB = v > 32 ? 32 : v;
        } else if constexpr (STG == 8) {
            Bb = g_k1 + ((size_t)z * NKC + c * 32) * LCP + by * 64; SB_ = LCP;
        } else {
            Bb = g_v1 + ((size_t)z * NKC + by * 64) * LCP + c * 32; SB_ = LCP;
        }
        if constexpr (Cfg<STG>::TRB) {
            int kk = tid >> 3, n0 = (tid & 7) * 8;
            bool ok = kk < vbB;
            const float* p = Bb + (long)kk * SB_ + n0;
#pragma unroll
            for (int j = 0; j < 2; ++j)
                vb4[j] = ok ? *(const float4*)(p + j * 4) : make_float4(0.f, 0.f, 0.f, 0.f);
        } else {
            int r = tid >> 2, cq = (tid & 3) * 8;
            bool ok = r < vrB;
            const float* p = Bb + (long)r * SB_ + cq;
#pragma unroll
            for (int j = 0; j < 2; ++j)
                vb4[j] = ok ? *(const float4*)(p + j * 4) : make_float4(0.f, 0.f, 0.f, 0.f);
        }
    };

    auto stash = [&](char* buf) {
        {
            int r = tid >> 1, cq = (tid & 1) * 16;
#pragma unroll
            for (int j = 0; j < 4; ++j) {
                uint2 hi, lo;
                cvt4(va[j], hi, lo);
                int el = r * 40 + cq + 4 * j;
                *(uint2*)(buf + AHOFF + el * 2) = hi;
                *(uint2*)(buf + ALOFF + el * 2) = lo;
            }
        }
        if constexpr (Cfg<STG>::TRB) {
            int kk = tid >> 3, n0 = (tid & 7) * 8;
#pragma unroll
            for (int j = 0; j < 2; ++j) {
                const float* fv = (const float*)&vb4[j];
#pragma unroll
                for (int e = 0; e < 4; ++e) {
                    float x = fv[e];
                    int el = (n0 + 4 * j + e) * 40 + kk;
                    __nv_bfloat16 h = __float2bfloat16(x);
                    __nv_bfloat16 l = __float2bfloat16(x - __bfloat162float(h));
                    *(__nv_bfloat16*)(buf + BHOFF + el * 2) = h;
                    *(__nv_bfloat16*)(buf + BLOFF + el * 2) = l;
                }
            }
        } else {
            int r = tid >> 2, cq = (tid & 3) * 8;
#pragma unroll
            for (int j = 0; j < 2; ++j) {
                uint2 hi, lo;
                cvt4(vb4[j], hi, lo);
                int el = r * 40 + cq + 4 * j;
                *(uint2*)(buf + BHOFF + el * 2) = hi;
                *(uint2*)(buf + BLOFF + el * 2) = lo;
            }
        }
    };

    float acc[2][4][4];
#pragma unroll
    for (int a = 0; a < 2; ++a)
#pragma unroll
        for (int b2 = 0; b2 < 4; ++b2)
#pragma unroll
            for (int e = 0; e < 4; ++e) acc[a][b2][e] = 0.f;

    int warpM = wid & 3, warpN = wid >> 2;

    gather(0);
    for (int c = 0; c < Cfg<STG>::NCH; ++c) {
        char* buf = smem + (c & 1) * BUFB;
        stash(buf);
        __syncthreads();
        if (c + 1 < Cfg<STG>::NCH) gather(c + 1);

        uint32_t sA = s2u(buf + AHOFF);
        uint32_t sB = s2u(buf + BHOFF);
#pragma unroll
        for (int kb = 0; kb < 2; ++kb) {
            uint32_t ah[2][4], al[2][4];
#pragma unroll
            for (int mi = 0; mi < 2; ++mi) {
                uint32_t addr = sA + ((warpM * 32 + mi * 16 + (lane & 15)) * 40 +
                                      kb * 16 + (lane >> 4) * 8) * 2;
                ldm4(ah[mi], addr);
                ldm4(al[mi], addr + (ALOFF - AHOFF));
            }
            uint32_t bh[2][4], bl[2][4];
#pragma unroll
            for (int g = 0; g < 2; ++g) {
                uint32_t addr = sB + ((warpN * 32 + g * 16 + (lane & 7) + ((lane >> 4) & 1) * 8) * 40 +
                                      kb * 16 + ((lane >> 3) & 1) * 8) * 2;
                ldm4(bh[g], addr);
                ldm4(bl[g], addr + (BLOFF - BHOFF));
            }
#pragma unroll
            for (int mi = 0; mi < 2; ++mi)
#pragma unroll
                for (int ni = 0; ni < 4; ++ni) {
                    const uint32_t* bhf = &bh[ni >> 1][(ni & 1) * 2];
                    const uint32_t* blf = &bl[ni >> 1][(ni & 1) * 2];
                    mma16816(acc[mi][ni], ah[mi], bhf);
                    mma16816(acc[mi][ni], ah[mi], blf);
                    mma16816(acc[mi][ni], al[mi], bhf);
                }
        }
        __syncthreads();
    }

    int r0 = lane >> 2, c0 = (lane & 3) * 2;
#pragma unroll
    for (int mi = 0; mi < 2; ++mi)
#pragma unroll
        for (int rh = 0; rh < 2; ++rh) {
            int m = warpM * 32 + mi * 16 + r0 + rh * 8;
            float* dst = nullptr;
            bool ok = true;
            int vmax = 64;
            float bias = 0.f;
            if constexpr (STG <= 2) {
                float* outp = (STG == 0) ? g_q1 : (STG == 1) ? g_k1 : g_v1;
                dst = outp + ((size_t)z * NKC + bx * 128 + m) * LCP + by * 64;
                int v = LC - by * 64; vmax = v > 64 ? 64 : v;
                bias = p2[bx * 128 + m];
            } else if constexpr (STG == 5) {
                int l = bx * 128 + m; ok = l < LC;
                dst = g_t1 + ((size_t)z * LC + l) * ADIM + by * 64;
            } else if constexpr (STG == 6) {
                dst = g_sc + ((size_t)z * NLB + bx * 128 + m) * LCP + by * 64;
                int v = LC - by * 64; vmax = v > 64 ? 64 : v;
            } else if constexpr (STG == 7) {
                dst = g_o1 + ((size_t)z * NLB + bx * 128 + m) * NKC + by * 64;
            } else if constexpr (STG == 8) {
                dst = g_b2s + ((size_t)z * NLB + bx * 128 + m) * LCP + by * 64;
                int v = LC - by * 64; vmax = v > 64 ? 64 : v;
            } else {
                dst = g_o2 + ((size_t)z * NLB + bx * 128 + m) * NKC + by * 64;
            }
            if (!ok) continue;
#pragma unroll
            for (int ni = 0; ni < 4; ++ni) {
                int col = warpN * 32 + ni * 8 + c0;
                if (col < vmax) {
                    float v0 = acc[mi][ni][rh * 2 + 0];
                    float v1 = acc[mi][ni][rh * 2 + 1];
                    if constexpr (STG <= 2) {
                        v0 += bias; v1 += bias;
                        v0 = v0 > 0.f ? v0 : (__expf(v0) - 1.f);
                        v1 = v1 > 0.f ? v1 : (__expf(v1) - 1.f);
                    }
                    if constexpr (STG == 5) { v0 = tanhf(v0); v1 = tanhf(v1); }
                    *(float2*)(dst + col) = make_float2(v0, v1);
                }
            }
        }
}

// ---------- weight repack: g_wrep[t][o][i] = w[o][i][t] ----------
__global__ void repack_w(const float* __restrict__ w) {
    int idx = blockIdx.x * 256 + threadIdx.x;
    if (idx < NKC * DIN) {
        g_wrep[idx]                 = w[idx * 3 + 0];
        g_wrep[NKC * DIN + idx]     = w[idx * 3 + 1];
        g_wrep[2 * NKC * DIN + idx] = w[idx * 3 + 2];
    }
}

// ---------- softmax over rows of length 1022 (stride 1024) ----------
__global__ void softmax_kernel(int sel) {
    float* base = (sel == 1) ? g_sc : g_b2s;
    float* row = base + ((size_t)blockIdx.y * 1024 + blockIdx.x) * 1024;
    int tid = threadIdx.x;
    float v[4];
    float mx = -1e30f;
#pragma unroll
    for (int j = 0; j < 4; ++j) {
        int idx = tid + j * 256;
        v[j] = (idx < LC) ? row[idx] : -1e30f;
        mx = fmaxf(mx, v[j]);
    }
    __shared__ float red[256];
    red[tid] = mx; __syncthreads();
    for (int s = 128; s > 0; s >>= 1) { if (tid < s) red[tid] = fmaxf(red[tid], red[tid + s]); __syncthreads(); }
    mx = red[0]; __syncthreads();
    float sum = 0.f;
#pragma unroll
    for (int j = 0; j < 4; ++j) {
        int idx = tid + j * 256;
        v[j] = (idx < LC) ? __expf(v[j] - mx) : 0.f;
        sum += v[j];
    }
    red[tid] = sum; __syncthreads();
    for (int s = 128; s > 0; s >>= 1) { if (tid < s) red[tid] += red[tid + s]; __syncthreads(); }
    float inv = 1.f / red[0];
#pragma unroll
    for (int j = 0; j < 4; ++j) {
        int idx = tid + j * 256;
        if (idx < LC) row[idx] = v[j] * inv;
    }
}

// ---------- l2norm + concat ----------
__global__ void l2norm_kernel(float* __restrict__ out) {
    int row = blockIdx.x;
    const float* src = ((blockIdx.y == 0) ? g_o1 : g_o2) + (size_t)row * NKC;
    int tid = threadIdx.x;
    float4 v = ((const float4*)src)[tid];
    float ss = v.x * v.x + v.y * v.y + v.z * v.z + v.w * v.w;
    __shared__ float red[128];
    red[tid] = ss; __syncthreads();
    for (int s = 64; s > 0; s >>= 1) { if (tid < s) red[tid] += red[tid + s]; __syncthreads(); }
    float inv = 1.f / fmaxf(sqrtf(red[0]), 1e-12f);
    ((float4*)(out + (size_t)row * 1024 + blockIdx.y * NKC))[tid] =
        make_float4(v.x * inv, v.y * inv, v.z * inv, v.w * inv);
}

// ---------- launch ----------
extern "C" void kernel_launch(void* const* d_in, const int* in_sizes, int n_in,
                              void* d_out, int out_size) {
    (void)in_sizes; (void)n_in; (void)out_size;
    const float* emb = (const float*)d_in[0];
    const float* lab = (const float*)d_in[1];
    const float* wq  = (const float*)d_in[2];
    const float* bq  = (const float*)d_in[3];
    const float* wk  = (const float*)d_in[4];
    const float* bk  = (const float*)d_in[5];
    const float* wv  = (const float*)d_in[6];
    const float* bv  = (const float*)d_in[7];
    const float* w1  = (const float*)d_in[8];
    const float* w2  = (const float*)d_in[9];
    float* out = (float*)d_out;

    cudaFuncSetAttribute(gtc<0>, cudaFuncAttributeMaxDynamicSharedMemorySize, SMEMB);
    cudaFuncSetAttribute(gtc<1>, cudaFuncAttributeMaxDynamicSharedMemorySize, SMEMB);
    cudaFuncSetAttribute(gtc<2>, cudaFuncAttributeMaxDynamicSharedMemorySize, SMEMB);
    cudaFuncSetAttribute(gtc<5>, cudaFuncAttributeMaxDynamicSharedMemorySize, SMEMB);
    cudaFuncSetAttribute(gtc<6>, cudaFuncAttributeMaxDynamicSharedMemorySize, SMEMB);
    cudaFuncSetAttribute(gtc<7>, cudaFuncAttributeMaxDynamicSharedMemorySize, SMEMB);
    cudaFuncSetAttribute(gtc<8>, cudaFuncAttributeMaxDynamicSharedMemorySize, SMEMB);
    cudaFuncSetAttribute(gtc<9>, cudaFuncAttributeMaxDynamicSharedMemorySize, SMEMB);
    cudaFuncSetAttribute(flash_attn, cudaFuncAttributeMaxDynamicSharedMemorySize, FSM);

    dim3 thr(256);
    repack_w<<<1024, 256>>>(wq);
    gtc<0><<<dim3(4, 16, 16), thr, SMEMB>>>(emb, bq);
    repack_w<<<1024, 256>>>(wk);
    gtc<1><<<dim3(4, 16, 16), thr, SMEMB>>>(emb, bk);
    repack_w<<<1024, 256>>>(wv);
    gtc<2><<<dim3(4, 16, 16), thr, SMEMB>>>(emb, bv);

    flash_attn<<<dim3(8, 128), thr, FSM>>>();

    gtc<5><<<dim3(8, 4, 16), thr, SMEMB>>>(w1, nullptr);
    gtc<6><<<dim3(8, 16, 16), thr, SMEMB>>>(w2, nullptr);
    softmax_kernel<<<dim3(1024, 16), thr>>>(1);
    gtc<7><<<dim3(8, 8, 16), thr, SMEMB>>>(nullptr, nullptr);

    gtc<8><<<dim3(8, 16, 16), thr, SMEMB>>>(lab, nullptr);
    softmax_kernel<<<dim3(1024, 16), thr>>>(2);
    gtc<9><<<dim3(8, 8, 16), thr, SMEMB>>>(nullptr, nullptr);

    l2norm_kernel<<<dim3(16384, 2), dim3(128)>>>(out);
}